// round 14
// baseline (speedup 1.0000x reference)
#include <cuda_runtime.h>
#include <cuda_bf16.h>
#include <math.h>
#include <stdint.h>

#define NRAYS 8192
#define SMAX  64

// ---------------- global scratch ----------------
__device__ int      g_cnt[NRAYS];
__device__ int      g_off[NRAYS + 1];
__device__ int      g_pray[NRAYS * SMAX];
__device__ float    g_vemb[NRAYS * 27];
__device__ float    g_sig[NRAYS * SMAX];
__device__ float    g_rgbp[NRAYS * SMAX * 3];
__device__ uint4    g_wimg4[11776];   // packed bf16 hi/lo weight image (47104 words), 16B aligned
__device__ int      g_tile_ctr;

// image layout (u32 words): per (kstep s, Mtile mt): 256 words =
// [hi: lane*4+reg (128)][lo: 128 + lane*4+reg]; blocks ordered blk = s*MT + mt.
// words: L1@0 (MT8,S2) | L2@4096 (MT8,S8) | L3@20480 (MT8,S8) | L4@36864 (MT4,S10)

__device__ __forceinline__ uint32_t sptr(const void* p) {
    return (uint32_t)__cvta_generic_to_shared(p);
}
__device__ __forceinline__ uint32_t packsplit(float y) {
    unsigned short h = __bfloat16_as_ushort(__float2bfloat16(y));
    float hf = __uint_as_float((uint32_t)h << 16);
    unsigned short l = __bfloat16_as_ushort(__float2bfloat16(y - hf));
    return ((uint32_t)h << 16) | l;
}
__device__ __forceinline__ void mma_bf16(float (&c)[4], const uint32_t (&a)[4],
                                         uint32_t b0, uint32_t b1) {
    asm volatile("mma.sync.aligned.m16n8k16.row.col.f32.bf16.bf16.f32 "
        "{%0,%1,%2,%3}, {%4,%5,%6,%7}, {%8,%9}, {%0,%1,%2,%3};"
        : "+f"(c[0]), "+f"(c[1]), "+f"(c[2]), "+f"(c[3])
        : "r"(a[0]), "r"(a[1]), "r"(a[2]), "r"(a[3]), "r"(b0), "r"(b1));
}
__device__ __forceinline__ void cpa16(uint32_t dsm, const void* gsrc) {
    asm volatile("cp.async.cg.shared.global [%0], [%1], 16;"
                 :: "r"(dsm), "l"(__cvta_generic_to_global(gsrc)) : "memory");
}
#define CP_COMMIT() asm volatile("cp.async.commit_group;" ::: "memory")
#define CP_WAIT(n)  asm volatile("cp.async.wait_group %0;" :: "n"(n) : "memory")

// ---------------- fused setup: wimg (blocks 0..183) + per-ray prep (blocks 184..215) ----
__global__ void setup_kernel(const float* __restrict__ W1, const float* __restrict__ W2,
                             const float* __restrict__ Wf, const float* __restrict__ Wc1,
                             const int* __restrict__ p2v, const float* __restrict__ rays_d) {
    if (blockIdx.x < 184) {
        int idx = blockIdx.x * 256 + threadIdx.x;
        if (idx >= 47104) return;
        int layer, rel, MT;
        if (idx < 4096)       { layer = 0; rel = idx;         MT = 8; }
        else if (idx < 20480) { layer = 1; rel = idx - 4096;  MT = 8; }
        else if (idx < 36864) { layer = 2; rel = idx - 20480; MT = 8; }
        else                  { layer = 3; rel = idx - 36864; MT = 4; }
        int blk = rel >> 8, within = rel & 255;
        int half = within >> 7, lr = within & 127;
        int lane = lr >> 2, r = lr & 3;
        int s = blk / MT, mt = blk % MT;
        int g = lane >> 2, tg = lane & 3;
        int row = g + (r & 1) * 8;
        int kk = 2 * tg + (r >> 1) * 8;
        int u = mt * 16 + row;
        int k = s * 16 + kk;
        float x0, x1;
        if (layer == 0)      { x0 = W1[k * 128 + u]; x1 = W1[(k + 1) * 128 + u]; }
        else if (layer == 1) { x0 = W2[k * 128 + u]; x1 = W2[(k + 1) * 128 + u]; }
        else if (layer == 2) { x0 = Wf[k * 128 + u]; x1 = Wf[(k + 1) * 128 + u]; }
        else { x0 = (k < 155) ? Wc1[k * 64 + u] : 0.f; x1 = (k + 1 < 155) ? Wc1[(k + 1) * 64 + u] : 0.f; }
        unsigned short h0 = __bfloat16_as_ushort(__float2bfloat16(x0));
        unsigned short h1 = __bfloat16_as_ushort(__float2bfloat16(x1));
        uint32_t w;
        if (half == 0) {
            w = ((uint32_t)h1 << 16) | h0;
        } else {
            float r0 = x0 - __uint_as_float((uint32_t)h0 << 16);
            float r1 = x1 - __uint_as_float((uint32_t)h1 << 16);
            unsigned short l0 = __bfloat16_as_ushort(__float2bfloat16(r0));
            unsigned short l1 = __bfloat16_as_ushort(__float2bfloat16(r1));
            w = ((uint32_t)l1 << 16) | l0;
        }
        ((uint32_t*)g_wimg4)[idx] = w;
    } else {
        int r = (blockIdx.x - 184) * 256 + threadIdx.x;
        if (r >= NRAYS) return;
        int lo = 0, hi = SMAX;
        while (lo < hi) {                   // valid samples form a prefix
            int mid = (lo + hi) >> 1;
            if (p2v[r * SMAX + mid] >= 0) lo = mid + 1; else hi = mid;
        }
        g_cnt[r] = lo;
        float dv[3] = {rays_d[r * 3], rays_d[r * 3 + 1], rays_d[r * 3 + 2]};
        g_vemb[r * 27 + 0] = dv[0]; g_vemb[r * 27 + 1] = dv[1]; g_vemb[r * 27 + 2] = dv[2];
#pragma unroll
        for (int i = 0; i < 3; i++)
#pragma unroll
            for (int l = 0; l < 4; l++) {
                float ang = dv[i] * (float)(1 << l);
                g_vemb[r * 27 + 3 + i * 4 + l]  = sinf(ang);
                g_vemb[r * 27 + 15 + i * 4 + l] = cosf(ang);
            }
    }
}

__global__ void scan_kernel() {
    __shared__ int wsum[32];
    int t = threadIdx.x;
    int v[8]; int s = 0;
#pragma unroll
    for (int i = 0; i < 8; i++) { v[i] = g_cnt[t * 8 + i]; s += v[i]; }
    int lane = t & 31, wid = t >> 5;
    int x = s;
#pragma unroll
    for (int d = 1; d < 32; d <<= 1) { int y = __shfl_up_sync(0xffffffffu, x, d); if (lane >= d) x += y; }
    if (lane == 31) wsum[wid] = x;
    __syncthreads();
    if (wid == 0) {
        int y = wsum[lane];
#pragma unroll
        for (int d = 1; d < 32; d <<= 1) { int z = __shfl_up_sync(0xffffffffu, y, d); if (lane >= d) y += z; }
        wsum[lane] = y;
    }
    __syncthreads();
    int run = (wid > 0 ? wsum[wid - 1] : 0) + x - s;
#pragma unroll
    for (int i = 0; i < 8; i++) { g_off[t * 8 + i] = run; run += v[i]; }
    if (t == 1023) { g_off[NRAYS] = run; g_tile_ctr = 0; }
}

__global__ void pray_kernel() {
    int r = blockIdx.x * 4 + (threadIdx.x >> 6);
    int t = threadIdx.x & 63;
    int o = g_off[r], c = g_off[r + 1] - o;
    if (t < c) g_pray[o + t] = r;
}

// ---------------- MLP kernel ----------------
// smem word offsets
#define BUFA_W  0        // [64 pts][136] packed hi/lo words (X0:K32, h2:K128) / c1 fp32 [64][68]
#define BUFB_W  8704     // [64 pts][168] packed (h1:K128, feat+vemb:K160)
#define WBUF_W  19456    // 3 x 2048-word cp.async stages
#define SB1_W   25600
#define SB2_W   25728
#define SBF_W   25856
#define SBC1_W  25984
#define SWSIG_W 26048
#define SWC2_W  26176
#define SWPTS_W 26368
#define SBC2_W  26464
#define SBSIG_W 26467
#define SPX_W   26468
#define SPY_W   26532
#define SPZ_W   26596
#define SVOX_W  26660
#define SRAY_W  26724
#define SCUR_W  26788
#define SMEM_WORDS 26792
#define SMEM_MLP_BYTES (SMEM_WORDS * 4)

#define KPA 136   // 136 % 32 == 8 -> conflict-free B-frag LDS.64
#define KPB 168   // 168 % 32 == 8

template <int MT, int NSTEPS, int KPIN>
__device__ __forceinline__ void layer_mma(const uint4* __restrict__ gimg4,
                                          const uint32_t* __restrict__ wbuf, uint32_t wbsm,
                                          const uint32_t* __restrict__ xin,
                                          float (&C)[2][8][4],
                                          int tid, int wid, int lane) {
    constexpr int CH4 = MT * 64;          // uint4 per k16 chunk
    constexpr int LPT = CH4 / 128;        // uint4 per thread per stage (4 or 2)
    const int g = lane >> 2, tg = lane & 3;
#pragma unroll
    for (int a = 0; a < 2; a++)
#pragma unroll
        for (int b = 0; b < 8; b++)
#pragma unroll
            for (int c = 0; c < 4; c++) C[a][b][c] = 0.f;

    __syncthreads();   // wbuf reuse + xin producer ordering
    // prologue: stages 0 and 1 in flight
#pragma unroll
    for (int i = 0; i < LPT; i++)
        cpa16(wbsm + (uint32_t)(tid + i * 128) * 16u, gimg4 + tid + i * 128);
    CP_COMMIT();
    {
        const uint4* s1 = gimg4 + CH4;
#pragma unroll
        for (int i = 0; i < LPT; i++)
            cpa16(wbsm + 8192u + (uint32_t)(tid + i * 128) * 16u, s1 + tid + i * 128);
        CP_COMMIT();
    }
#pragma unroll 1
    for (int s = 0; s < NSTEPS; s++) {
        if (s + 1 < NSTEPS) { CP_WAIT(1); } else { CP_WAIT(0); }
        __syncthreads();
        if (s + 2 < NSTEPS) {
            const uint4* src = gimg4 + (s + 2) * CH4;
            uint32_t dsm = wbsm + (uint32_t)(((s + 2) % 3) * 8192);
#pragma unroll
            for (int i = 0; i < LPT; i++)
                cpa16(dsm + (uint32_t)(tid + i * 128) * 16u, src + tid + i * 128);
            CP_COMMIT();
        }
        const uint32_t* wb = wbuf + (s % 3) * 2048;
        uint32_t Ahi[2][4], Alo[2][4];
        const int NMI = (MT == 8) ? 2 : 1;
#pragma unroll
        for (int mi = 0; mi < NMI; mi++) {
            int mt = (MT == 8) ? (wid + mi * 4) : wid;
            const uint32_t* fb = wb + mt * 256;
            *(uint4*)Ahi[mi] = *(const uint4*)(fb + lane * 4);
            *(uint4*)Alo[mi] = *(const uint4*)(fb + 128 + lane * 4);
        }
        const uint32_t* xk = xin + s * 16 + 2 * tg;
#pragma unroll
        for (int nt = 0; nt < 8; nt++) {
            int pt = nt * 8 + g;
            const uint32_t* xr = xk + pt * KPIN;
            uint2 d0 = *(const uint2*)xr;
            uint2 d1 = *(const uint2*)(xr + 8);
            uint32_t bh0 = __byte_perm(d0.x, d0.y, 0x7632);
            uint32_t bl0 = __byte_perm(d0.x, d0.y, 0x5410);
            uint32_t bh1 = __byte_perm(d1.x, d1.y, 0x7632);
            uint32_t bl1 = __byte_perm(d1.x, d1.y, 0x5410);
#pragma unroll
            for (int mi = 0; mi < NMI; mi++) {
                mma_bf16(C[mi][nt], Ahi[mi], bh0, bh1);
                mma_bf16(C[mi][nt], Ahi[mi], bl0, bl1);
                mma_bf16(C[mi][nt], Alo[mi], bh0, bh1);
            }
        }
    }
}

template <int MTILES, bool RELU>
__device__ __forceinline__ void epi_pack(float (&C)[2][8][4], const float* __restrict__ bias,
                                         uint32_t* __restrict__ xout, int KPOUT,
                                         int wid, int lane) {
    int g = lane >> 2, tg = lane & 3;
#pragma unroll
    for (int mi = 0; mi < MTILES; mi++) {
        int mt = (MTILES == 2) ? (wid + mi * 4) : wid;
        int r0 = mt * 16 + g, r1 = r0 + 8;
        float b0 = bias[r0], b1 = bias[r1];
#pragma unroll
        for (int nt = 0; nt < 8; nt++) {
            int p0 = nt * 8 + 2 * tg;
            float y00 = C[mi][nt][0] + b0, y01 = C[mi][nt][1] + b0;
            float y10 = C[mi][nt][2] + b1, y11 = C[mi][nt][3] + b1;
            if (RELU) {
                y00 = fmaxf(y00, 0.f); y01 = fmaxf(y01, 0.f);
                y10 = fmaxf(y10, 0.f); y11 = fmaxf(y11, 0.f);
            }
            xout[p0 * KPOUT + r0]       = packsplit(y00);
            xout[(p0 + 1) * KPOUT + r0] = packsplit(y01);
            xout[p0 * KPOUT + r1]       = packsplit(y10);
            xout[(p0 + 1) * KPOUT + r1] = packsplit(y11);
        }
    }
}

__global__ void __launch_bounds__(128, 2)
mlp_kernel(const float* __restrict__ pts, const int* __restrict__ p2v,
           const float* __restrict__ vox_emb, const float* __restrict__ Wpts,
           const float* __restrict__ b1, const float* __restrict__ b2,
           const float* __restrict__ Wsig, const float* __restrict__ bsig,
           const float* __restrict__ bfeat, const float* __restrict__ bc1,
           const float* __restrict__ Wc2, const float* __restrict__ bc2) {
    extern __shared__ uint32_t smu[];
    float* smf = (float*)smu;
    uint32_t* bufA = smu + BUFA_W;
    uint32_t* bufB = smu + BUFB_W;
    uint32_t* wbuf = smu + WBUF_W;
    const uint32_t wbsm = sptr(wbuf);
    float* c1f = (float*)(smu + BUFA_W);
    int* voxs   = (int*)(smu + SVOX_W);
    int* rays_s = (int*)(smu + SRAY_W);
    int* curp   = (int*)(smu + SCUR_W);
    const int tid = threadIdx.x;
    const int wid = tid >> 5, lane = tid & 31;

    for (int i = tid; i < 128; i += 128) {
        smf[SB1_W + i] = b1[i]; smf[SB2_W + i] = b2[i];
        smf[SBF_W + i] = bfeat[i]; smf[SWSIG_W + i] = Wsig[i];
    }
    if (tid < 64) smf[SBC1_W + tid] = bc1[tid];
    if (tid < 96) smf[SWPTS_W + tid] = Wpts[tid];
    for (int i = tid; i < 192; i += 128) smf[SWC2_W + i] = Wc2[i];
    if (tid < 3)  smf[SBC2_W + tid] = bc2[tid];
    if (tid == 0) smf[SBSIG_W] = bsig[0];

    const int P = g_off[NRAYS];
    const int ntiles = (P + 63) >> 6;
    float C[2][8][4];

    while (true) {
        __syncthreads();
        if (tid == 0) *curp = atomicAdd(&g_tile_ctr, 1);
        __syncthreads();
        const int tile = *curp;
        if (tile >= ntiles) break;
        const int pbase = tile * 64;
        const int np = min(64, P - pbase);

        // ---- tile meta ----
        if (tid < 64) {
            if (tid < np) {
                int pid = pbase + tid;
                int ray = g_pray[pid];
                int base = ray * SMAX + (pid - g_off[ray]);
                voxs[tid] = p2v[base];
                smf[SPX_W + tid] = pts[base * 3];
                smf[SPY_W + tid] = pts[base * 3 + 1];
                smf[SPZ_W + tid] = pts[base * 3 + 2];
                rays_s[tid] = ray;
            } else {
                voxs[tid] = 0; rays_s[tid] = 0;
                smf[SPX_W + tid] = 0.f; smf[SPY_W + tid] = 0.f; smf[SPZ_W + tid] = 0.f;
            }
        }
        __syncthreads();

        // ---- embed -> bufA [pt][k<32]; vemb -> bufB [pt][128+j] ----
        {
            int pt = tid >> 1, kh = (tid & 1) * 16;
            int v = voxs[pt];
            float px = smf[SPX_W + pt], py = smf[SPY_W + pt], pz = smf[SPZ_W + pt];
            const float* vrow = vox_emb + (size_t)v * 32;
#pragma unroll
            for (int q = 0; q < 16; q++) {
                int k = kh + q;
                float val = vrow[k] + px * smf[SWPTS_W + k]
                          + py * smf[SWPTS_W + 32 + k] + pz * smf[SWPTS_W + 64 + k];
                bufA[pt * KPA + k] = packsplit(val);
            }
            int ray = rays_s[pt];
#pragma unroll
            for (int q = 0; q < 16; q++) {
                int j = kh + q;
                float val = (j < 27) ? g_vemb[ray * 27 + j] : 0.f;
                bufB[pt * KPB + 128 + j] = packsplit(val);
            }
        }
        // (layer_mma's entry sync orders these writes before mma reads)

        layer_mma<8, 2, KPA>(g_wimg4,        wbuf, wbsm, bufA, C, tid, wid, lane);   // h1
        epi_pack<2, true>(C, smf + SB1_W, bufB, KPB, wid, lane);
        layer_mma<8, 8, KPB>(g_wimg4 + 1024, wbuf, wbsm, bufB, C, tid, wid, lane);   // h2
        epi_pack<2, true>(C, smf + SB2_W, bufA, KPA, wid, lane);
        __syncthreads();

        // ---- sigma from h2 (bufA packed) ----
        if (tid < np) {
            float a = smf[SBSIG_W];
#pragma unroll 8
            for (int k = 0; k < 128; k++) {
                uint32_t w = bufA[tid * KPA + k];
                float val = __uint_as_float(w & 0xffff0000u) + __uint_as_float(w << 16);
                a += val * smf[SWSIG_W + k];
            }
            g_sig[pbase + tid] = a;
        }

        layer_mma<8, 8, KPA>(g_wimg4 + 5120, wbuf, wbsm, bufA, C, tid, wid, lane);   // feat
        epi_pack<2, false>(C, smf + SBF_W, bufB, KPB, wid, lane);
        layer_mma<4, 10, KPB>(g_wimg4 + 9216, wbuf, wbsm, bufB, C, tid, wid, lane);  // c1
        // L4 epilogue: fp32 c1 -> bufA as float [pt][68]
        {
            int g = lane >> 2, tg = lane & 3;
            int r0 = wid * 16 + g, r1 = r0 + 8;
            float bb0 = smf[SBC1_W + r0], bb1 = smf[SBC1_W + r1];
#pragma unroll
            for (int nt = 0; nt < 8; nt++) {
                int p0 = nt * 8 + 2 * tg;
                c1f[p0 * 68 + r0]       = fmaxf(C[0][nt][0] + bb0, 0.f);
                c1f[(p0 + 1) * 68 + r0] = fmaxf(C[0][nt][1] + bb0, 0.f);
                c1f[p0 * 68 + r1]       = fmaxf(C[0][nt][2] + bb1, 0.f);
                c1f[(p0 + 1) * 68 + r1] = fmaxf(C[0][nt][3] + bb1, 0.f);
            }
        }
        __syncthreads();

        // ---- rgb = c1 @ Wc2 + bc2 ----
        if (tid < np) {
            float a0 = smf[SBC2_W], a1 = smf[SBC2_W + 1], a2 = smf[SBC2_W + 2];
#pragma unroll 8
            for (int u = 0; u < 64; u++) {
                float cv = c1f[tid * 68 + u];
                a0 += cv * smf[SWC2_W + u * 3];
                a1 += cv * smf[SWC2_W + u * 3 + 1];
                a2 += cv * smf[SWC2_W + u * 3 + 2];
            }
            size_t o3 = (size_t)(pbase + tid) * 3;
            g_rgbp[o3] = a0; g_rgbp[o3 + 1] = a1; g_rgbp[o3 + 2] = a2;
        }
    }
}

// ---------------- render: one warp per ray ----------------
__global__ void render_kernel(const float* __restrict__ t_vals, const float* __restrict__ dists,
                              float* __restrict__ out) {
    int gw = (blockIdx.x * blockDim.x + threadIdx.x) >> 5;
    int lane = threadIdx.x & 31;
    if (gw >= NRAYS) return;
    int off = g_off[gw], c = g_off[gw + 1] - off;

    float fe0 = 0.f, fe1 = 0.f, r0 = 0.f, g0 = 0.f, b0 = 0.f, r1 = 0.f, g1 = 0.f, b1v = 0.f;
    float t0 = 0.f, t1 = 0.f;
    if (lane < c) {
        fe0 = fmaxf(g_sig[off + lane], 0.f) * dists[gw * SMAX + lane];
        r0 = g_rgbp[(size_t)(off + lane) * 3];
        g0 = g_rgbp[(size_t)(off + lane) * 3 + 1];
        b0 = g_rgbp[(size_t)(off + lane) * 3 + 2];
        t0 = t_vals[gw * SMAX + lane];
    }
    int s1 = lane + 32;
    if (s1 < c) {
        fe1 = fmaxf(g_sig[off + s1], 0.f) * dists[gw * SMAX + s1];
        r1 = g_rgbp[(size_t)(off + s1) * 3];
        g1 = g_rgbp[(size_t)(off + s1) * 3 + 1];
        b1v = g_rgbp[(size_t)(off + s1) * 3 + 2];
        t1 = t_vals[gw * SMAX + s1];
    }
    float i0 = fe0;
#pragma unroll
    for (int d = 1; d < 32; d <<= 1) { float y = __shfl_up_sync(0xffffffffu, i0, d); if (lane >= d) i0 += y; }
    float tot0 = __shfl_sync(0xffffffffu, i0, 31);
    float i1 = fe1;
#pragma unroll
    for (int d = 1; d < 32; d <<= 1) { float y = __shfl_up_sync(0xffffffffu, i1, d); if (lane >= d) i1 += y; }
    float w0 = (1.f - expf(-fe0)) * expf(-(i0 - fe0));
    float w1 = (1.f - expf(-fe1)) * expf(-(tot0 + i1 - fe1));

    float cr = w0 * (r0 + 1.f) * 0.5f + w1 * (r1 + 1.f) * 0.5f;
    float cg = w0 * (g0 + 1.f) * 0.5f + w1 * (g1 + 1.f) * 0.5f;
    float cb = w0 * (b0 + 1.f) * 0.5f + w1 * (b1v + 1.f) * 0.5f;
    float ac = w0 + w1;
    float dp = w0 * t0 + w1 * t1;
#pragma unroll
    for (int d = 16; d; d >>= 1) {
        cr += __shfl_xor_sync(0xffffffffu, cr, d);
        cg += __shfl_xor_sync(0xffffffffu, cg, d);
        cb += __shfl_xor_sync(0xffffffffu, cb, d);
        ac += __shfl_xor_sync(0xffffffffu, ac, d);
        dp += __shfl_xor_sync(0xffffffffu, dp, d);
    }
    if (lane == 0) {
        if (c > 0) {
            float disp = 1.f / fmaxf(1e-10f, dp / fmaxf(ac, 1e-10f));
            out[gw * 3] = cr; out[gw * 3 + 1] = cg; out[gw * 3 + 2] = cb;
            out[3 * NRAYS + gw] = disp;
            out[4 * NRAYS + gw] = ac;
        } else {
            out[gw * 3] = 0.f; out[gw * 3 + 1] = 0.f; out[gw * 3 + 2] = 0.f;
            out[3 * NRAYS + gw] = 0.f;
            out[4 * NRAYS + gw] = 0.f;
        }
    }
}

extern "C" void kernel_launch(void* const* d_in, const int* in_sizes, int n_in,
                              void* d_out, int out_size) {
    const float *rays_d = 0, *pts = 0, *t_vals = 0, *dists = 0, *vox = 0, *Wpts = 0;
    const float *W1 = 0, *b1 = 0, *W2 = 0, *b2 = 0, *Wsig = 0, *bsig = 0;
    const float *Wfeat = 0, *bfeat = 0, *Wc1 = 0, *bc1 = 0, *Wc2 = 0, *bc2 = 0;
    const int* p2v = 0;
    int n524 = 0, n16384 = 0, n128 = 0;
    for (int i = 0; i < n_in; i++) {
        const void* p = d_in[i];
        switch (in_sizes[i]) {
            case 24576:   rays_d = (const float*)p; break;
            case 1572864: pts    = (const float*)p; break;
            case 524288:
                if (n524 == 0) t_vals = (const float*)p;
                else if (n524 == 1) dists = (const float*)p;
                else p2v = (const int*)p;
                n524++; break;
            case 3200000: vox = (const float*)p; break;
            case 96:    Wpts = (const float*)p; break;
            case 4096:  W1 = (const float*)p; break;
            case 128:
                if (n128 == 0) b1 = (const float*)p;
                else if (n128 == 1) b2 = (const float*)p;
                else if (n128 == 2) Wsig = (const float*)p;
                else bfeat = (const float*)p;
                n128++; break;
            case 16384:
                if (n16384 == 0) W2 = (const float*)p; else Wfeat = (const float*)p;
                n16384++; break;
            case 1:    bsig = (const float*)p; break;
            case 9920: Wc1 = (const float*)p; break;
            case 64:   bc1 = (const float*)p; break;
            case 192:  Wc2 = (const float*)p; break;
            case 3:    bc2 = (const float*)p; break;
            default: break; // 8192 = ray_hits, derived from p2v
        }
    }
    static int smem_set = 0;
    if (!smem_set) {
        cudaFuncSetAttribute(mlp_kernel, cudaFuncAttributeMaxDynamicSharedMemorySize, SMEM_MLP_BYTES);
        smem_set = 1;
    }
    setup_kernel<<<216, 256>>>(W1, W2, Wfeat, Wc1, p2v, rays_d);
    scan_kernel<<<1, 1024>>>();
    pray_kernel<<<NRAYS / 4, 256>>>();
    mlp_kernel<<<296, 128, SMEM_MLP_BYTES>>>(pts, p2v, vox, Wpts, b1, b2, Wsig, bsig,
                                             bfeat, bc1, Wc2, bc2);
    render_kernel<<<NRAYS / 8, 256>>>(t_vals, dists, (float*)d_out);
}